// round 12
// baseline (speedup 1.0000x reference)
#include <cuda_runtime.h>
#include <cuda_bf16.h>
#include <mma.h>
#include <cstdint>

using namespace nvcuda;

// ---------------- problem constants ----------------
constexpr int Bv   = 64;
constexpr int Hv   = 56;
constexpr int Wv   = 56;
constexpr int Cv   = 192;
constexpr int HEADS= 6;
constexpr int WS   = 7;
constexpr int SS   = 3;
constexpr int MLPD = 768;
constexpr int NT   = 49;
constexpr int HD   = 32;
constexpr int Lv   = Hv * Wv;         // 3136
constexpr int MT   = Bv * Lv;         // 200704 rows
constexpr float SCALE = 0.17677669529663687f;

// ---------------- device scratch ----------------
__device__ __nv_bfloat16 g_hwin[(size_t)MT * Cv];
__device__ __nv_bfloat16 g_Q[(size_t)MT * Cv];
__device__ __nv_bfloat16 g_K[(size_t)MT * Cv];
__device__ __nv_bfloat16 g_V[(size_t)MT * Cv];
__device__ __nv_bfloat16 g_attn[(size_t)MT * Cv];
__device__ float         g_x1[(size_t)MT * Cv];
__device__ __nv_bfloat16 g_h2n[(size_t)MT * Cv];
__device__ __nv_bfloat16 g_mid[(size_t)MT * MLPD];
__device__ __nv_bfloat16 g_wqkv[Cv * 3 * Cv];
__device__ __nv_bfloat16 g_wproj[Cv * Cv];
__device__ __nv_bfloat16 g_w1[Cv * MLPD];
__device__ __nv_bfloat16 g_w2[MLPD * Cv];
__device__ float         g_bmp[64 * HEADS * NT * 52];

// ---------------- cp.async helpers ----------------
__device__ __forceinline__ void cp16(void* d, const void* s) {
    unsigned sa = (unsigned)__cvta_generic_to_shared(d);
    asm volatile("cp.async.cg.shared.global [%0], [%1], 16;" :: "r"(sa), "l"(s));
}
#define CP_COMMIT() asm volatile("cp.async.commit_group;")
#define CP_WAIT0()  asm volatile("cp.async.wait_group 0;")
#define CP_WAIT1()  asm volatile("cp.async.wait_group 1;")

// ---------------- weight conversion fp32 -> bf16 ----------------
__global__ void cvt_weights(const float* __restrict__ qkvw,
                            const float* __restrict__ projw,
                            const float* __restrict__ w1,
                            const float* __restrict__ w2) {
    constexpr int n0 = Cv * 3 * Cv;
    constexpr int n1 = Cv * Cv;
    constexpr int n2 = Cv * MLPD;
    constexpr int n3 = MLPD * Cv;
    constexpr int tot = n0 + n1 + n2 + n3;
    for (int i = blockIdx.x * blockDim.x + threadIdx.x; i < tot;
         i += gridDim.x * blockDim.x) {
        if (i < n0)                  g_wqkv[i]             = __float2bfloat16(qkvw[i]);
        else if (i < n0 + n1)        g_wproj[i - n0]       = __float2bfloat16(projw[i - n0]);
        else if (i < n0 + n1 + n2)   g_w1[i - n0 - n1]     = __float2bfloat16(w1[i - n0 - n1]);
        else                         g_w2[i - n0 - n1 - n2]= __float2bfloat16(w2[i - n0 - n1 - n2]);
    }
}

// ---------------- shift-mask + padded bias table ----------------
__device__ __forceinline__ int reg3(int r) { return r < 49 ? 0 : (r < 53 ? 1 : 2); }

__global__ void bm_kernel(const float* __restrict__ rpb) {
    int e = blockIdx.x * blockDim.x + threadIdx.x;
    constexpr int TOT = 64 * HEADS * NT * 52;
    if (e >= TOT) return;
    int j   = e % 52;
    int i   = (e / 52) % NT;
    int h   = (e / (52 * NT)) % HEADS;
    int wi  = e / (52 * NT * HEADS);
    float v = 0.f;
    if (j < NT) {
        int wh = wi >> 3, ww = wi & 7;
        int ih = i / WS, iw = i - ih * WS;
        int jh = j / WS, jw = j - jh * WS;
        int idx = (ih - jh + WS - 1) * (2 * WS - 1) + (iw - jw + WS - 1);
        v = rpb[idx * HEADS + h];
        int li = reg3(wh * WS + ih) * 3 + reg3(ww * WS + iw);
        int lj = reg3(wh * WS + jh) * 3 + reg3(ww * WS + jw);
        if (li != lj) v -= 100.f;
    }
    g_bmp[e] = v;
}

// ---------------- LayerNorm kernels ----------------
__global__ void ln1_kernel(const float* __restrict__ x,
                           const float* __restrict__ g,
                           const float* __restrict__ b) {
    int warp = threadIdx.x >> 5, lane = threadIdx.x & 31;
    int m = blockIdx.x * 8 + warp;
    int win = m / NT, tok = m - win * NT;
    int bi  = win >> 6, wi = win & 63;
    int wh  = wi >> 3, ww = wi & 7;
    int ih  = tok / WS, iw = tok - ih * WS;
    int r   = (wh * WS + ih + SS) % Hv;
    int c   = (ww * WS + iw + SS) % Wv;
    const float* row = x + ((size_t)bi * Lv + r * Wv + c) * Cv;
    float v[6];
#pragma unroll
    for (int k = 0; k < 6; k++) v[k] = row[lane + 32 * k];
    float s = 0.f;
#pragma unroll
    for (int k = 0; k < 6; k++) s += v[k];
#pragma unroll
    for (int o = 16; o; o >>= 1) s += __shfl_xor_sync(0xffffffffu, s, o);
    float mean = s * (1.f / 192.f);
    float q = 0.f;
#pragma unroll
    for (int k = 0; k < 6; k++) { float d = v[k] - mean; q += d * d; }
#pragma unroll
    for (int o = 16; o; o >>= 1) q += __shfl_xor_sync(0xffffffffu, q, o);
    float rstd = rsqrtf(q * (1.f / 192.f) + 1e-5f);
#pragma unroll
    for (int k = 0; k < 6; k++) {
        int cc = lane + 32 * k;
        g_hwin[(size_t)m * Cv + cc] = __float2bfloat16((v[k] - mean) * rstd * g[cc] + b[cc]);
    }
}

__global__ void ln2_kernel(const float* __restrict__ g,
                           const float* __restrict__ b) {
    int warp = threadIdx.x >> 5, lane = threadIdx.x & 31;
    int m = blockIdx.x * 8 + warp;
    const float* row = g_x1 + (size_t)m * Cv;
    float v[6];
#pragma unroll
    for (int k = 0; k < 6; k++) v[k] = row[lane + 32 * k];
    float s = 0.f;
#pragma unroll
    for (int k = 0; k < 6; k++) s += v[k];
#pragma unroll
    for (int o = 16; o; o >>= 1) s += __shfl_xor_sync(0xffffffffu, s, o);
    float mean = s * (1.f / 192.f);
    float q = 0.f;
#pragma unroll
    for (int k = 0; k < 6; k++) { float d = v[k] - mean; q += d * d; }
#pragma unroll
    for (int o = 16; o; o >>= 1) q += __shfl_xor_sync(0xffffffffu, q, o);
    float rstd = rsqrtf(q * (1.f / 192.f) + 1e-5f);
#pragma unroll
    for (int k = 0; k < 6; k++) {
        int cc = lane + 32 * k;
        g_h2n[(size_t)m * Cv + cc] = __float2bfloat16((v[k] - mean) * rstd * g[cc] + b[cc]);
    }
}

// ---------------- attention: one block/window, cp.async head pipelining -----
constexpr int ATTN_SMEM = 52176;

__global__ __launch_bounds__(256) void attn_wmma() {
    extern __shared__ __align__(16) unsigned char sm[];
    __nv_bfloat16* Qs = (__nv_bfloat16*)(sm);
    __nv_bfloat16* Ks = (__nv_bfloat16*)(sm + 5120);
    __nv_bfloat16* Vs = (__nv_bfloat16*)(sm + 10240);
    float*         Ss = (float*)(sm + 15360);
    __nv_bfloat16* Ps = (__nv_bfloat16*)(sm + 32768);
    float*         Bms= (float*)(sm + 41984);
    float*         Os = Ss;

    int win = blockIdx.x;
    int wi  = win & 63;
    int tid = threadIdx.x, warp = tid >> 5, lane = tid & 31;

    auto loadQK = [&](int head) {
        size_t base = (size_t)(win * HEADS + head) * NT * HD;
        for (int id = tid; id < 196; id += 256) {
            int r = id >> 2, c8 = (id & 3) * 8;
            cp16(&Qs[r * 40 + c8], &g_Q[base + id * 8]);
            cp16(&Ks[r * 40 + c8], &g_K[base + id * 8]);
        }
    };
    auto loadV = [&](int head) {
        size_t base = (size_t)(win * HEADS + head) * NT * HD;
        for (int id = tid; id < 196; id += 256) {
            int r = id >> 2, c8 = (id & 3) * 8;
            cp16(&Vs[r * 40 + c8], &g_V[base + id * 8]);
        }
    };
    auto loadBM = [&](int head) {
        const float* src = g_bmp + (size_t)(wi * HEADS + head) * (NT * 52);
        for (int id = tid; id < 49 * 13; id += 256) {
            int r = id / 13, c4 = (id % 13) * 4;
            cp16(&Bms[r * 52 + c4], &src[r * 52 + c4]);
        }
    };

    for (int id = tid; id < 60; id += 256) {
        int r = 49 + (id >> 2), c8 = (id & 3) * 8;
        *(uint4*)&Vs[r * 40 + c8] = make_uint4(0, 0, 0, 0);
    }
    __syncthreads();
    loadQK(0); loadV(0); loadBM(0); CP_COMMIT();

    for (int head = 0; head < HEADS; head++) {
        CP_WAIT0();
        __syncthreads();

        {
            int mrow = (warp >> 1) * 16, ncol = (warp & 1) * 32;
            wmma::fragment<wmma::accumulator, 16, 16, 16, float> acc[2];
            wmma::fill_fragment(acc[0], 0.f);
            wmma::fill_fragment(acc[1], 0.f);
#pragma unroll
            for (int kk = 0; kk < 32; kk += 16) {
                wmma::fragment<wmma::matrix_a, 16, 16, 16, __nv_bfloat16, wmma::row_major> af;
                wmma::load_matrix_sync(af, &Qs[mrow * 40 + kk], 40);
#pragma unroll
                for (int j = 0; j < 2; j++) {
                    wmma::fragment<wmma::matrix_b, 16, 16, 16, __nv_bfloat16, wmma::col_major> bf;
                    wmma::load_matrix_sync(bf, &Ks[(ncol + j * 16) * 40 + kk], 40);
                    wmma::mma_sync(acc[j], af, bf, acc[j]);
                }
            }
#pragma unroll
            for (int j = 0; j < 2; j++)
                wmma::store_matrix_sync(&Ss[mrow * 68 + ncol + j * 16], acc[j], 68,
                                        wmma::mem_row_major);
        }
        __syncthreads();
        if (head + 1 < HEADS) { loadQK(head + 1); CP_COMMIT(); }

        for (int row = warp; row < NT; row += 8) {
            int j1 = lane + 32;
            float s0 = Ss[row * 68 + lane] + Bms[row * 52 + lane];
            float s1 = (j1 < NT) ? Ss[row * 68 + j1] + Bms[row * 52 + j1] : -1e30f;
            float mx = fmaxf(s0, s1);
#pragma unroll
            for (int o = 16; o; o >>= 1) mx = fmaxf(mx, __shfl_xor_sync(0xffffffffu, mx, o));
            float e0 = __expf(s0 - mx);
            float e1 = (j1 < NT) ? __expf(s1 - mx) : 0.f;
            float smv = e0 + e1;
#pragma unroll
            for (int o = 16; o; o >>= 1) smv += __shfl_xor_sync(0xffffffffu, smv, o);
            float inv = 1.f / smv;
            Ps[row * 72 + lane] = __float2bfloat16(e0 * inv);
            Ps[row * 72 + j1]   = __float2bfloat16(e1 * inv);
        }
        __syncthreads();
        if (head + 1 < HEADS) { loadBM(head + 1); CP_COMMIT(); }

        {
            int mrow = (warp >> 1) * 16, ncol = (warp & 1) * 16;
            wmma::fragment<wmma::accumulator, 16, 16, 16, float> acc;
            wmma::fill_fragment(acc, 0.f);
#pragma unroll
            for (int kk = 0; kk < 64; kk += 16) {
                wmma::fragment<wmma::matrix_a, 16, 16, 16, __nv_bfloat16, wmma::row_major> af;
                wmma::fragment<wmma::matrix_b, 16, 16, 16, __nv_bfloat16, wmma::row_major> bf;
                wmma::load_matrix_sync(af, &Ps[mrow * 72 + kk], 72);
                wmma::load_matrix_sync(bf, &Vs[kk * 40 + ncol], 40);
                wmma::mma_sync(acc, af, bf, acc);
            }
            wmma::store_matrix_sync(&Os[mrow * 36 + ncol], acc, 36, wmma::mem_row_major);
        }
        __syncthreads();
        if (head + 1 < HEADS) { loadV(head + 1); CP_COMMIT(); }

        if (tid < 196) {
            int r = tid >> 2, d0 = (tid & 3) * 8;
            const float* src = &Os[r * 36 + d0];
            float4 a = *(const float4*)&src[0];
            float4 b = *(const float4*)&src[4];
            __nv_bfloat16 o[8] = {
                __float2bfloat16(a.x), __float2bfloat16(a.y),
                __float2bfloat16(a.z), __float2bfloat16(a.w),
                __float2bfloat16(b.x), __float2bfloat16(b.y),
                __float2bfloat16(b.z), __float2bfloat16(b.w)};
            *(uint4*)&g_attn[((size_t)win * NT + r) * Cv + head * HD + d0] =
                *(const uint4*)o;
        }
    }
}

// ------ whole-K wmma GEMM, K=192, 128 threads, 4 warps of 64x48 (NTL=96) ----
// EPI 0: hwin @ wqkv, EPI 1: attn @ wproj, EPI 2: h2n @ w1
template <int EPI>
__global__ __launch_bounds__(128) void gemm_wk(const float* __restrict__ bias,
                                               const float* __restrict__ xin) {
    constexpr int K   = Cv;            // 192
    constexpr int N   = (EPI == 0) ? 3 * Cv : (EPI == 2) ? MLPD : Cv;
    constexpr int NTL = 96;
    constexpr int ASTR= K + 8;         // 200
    constexpr int BSTR= NTL + 8;       // 104
    constexpr int CST = NTL + 4;       // 100

    const __nv_bfloat16* __restrict__ A =
        (EPI == 0) ? g_hwin : (EPI == 1) ? g_attn : g_h2n;
    const __nv_bfloat16* __restrict__ Bm =
        (EPI == 0) ? g_wqkv : (EPI == 1) ? g_wproj : g_w1;

    extern __shared__ __align__(16) unsigned char smbuf[];
    __nv_bfloat16* As = (__nv_bfloat16*)smbuf;                     // [128][200]
    __nv_bfloat16* Bs = (__nv_bfloat16*)(smbuf + 128 * ASTR * 2);  // [192][104]
    float*         Cs = (float*)smbuf;                             // [128][100]

    const int tid = threadIdx.x;
    const int m0 = blockIdx.y * 128;
    const int n0 = blockIdx.x * NTL;
    const int warp = tid >> 5, wm = warp >> 1, wn = warp & 1;

    // single load phase (whole K)
    for (int id = tid; id < 128 * (K / 8); id += 128) {
        int r = id / (K / 8), c8 = (id % (K / 8)) * 8;
        cp16(&As[r * ASTR + c8], &A[(size_t)(m0 + r) * K + c8]);
    }
    for (int id = tid; id < K * (NTL / 8); id += 128) {
        int r = id / (NTL / 8), c8 = (id % (NTL / 8)) * 8;
        cp16(&Bs[r * BSTR + c8], &Bm[(size_t)r * N + n0 + c8]);
    }
    CP_COMMIT();
    CP_WAIT0();
    __syncthreads();

    // warp tile 64x48: 4 A frags, 3 B frags, 12 MMAs per k-step
    wmma::fragment<wmma::accumulator, 16, 16, 16, float> acc[4][3];
#pragma unroll
    for (int i = 0; i < 4; i++)
#pragma unroll
        for (int j = 0; j < 3; j++) wmma::fill_fragment(acc[i][j], 0.f);

#pragma unroll
    for (int kk = 0; kk < K; kk += 16) {
        wmma::fragment<wmma::matrix_a, 16, 16, 16, __nv_bfloat16, wmma::row_major> af[4];
        wmma::fragment<wmma::matrix_b, 16, 16, 16, __nv_bfloat16, wmma::row_major> bfr[3];
#pragma unroll
        for (int i = 0; i < 4; i++)
            wmma::load_matrix_sync(af[i], &As[(wm * 64 + i * 16) * ASTR + kk], ASTR);
#pragma unroll
        for (int j = 0; j < 3; j++)
            wmma::load_matrix_sync(bfr[j], &Bs[kk * BSTR + wn * 48 + j * 16], BSTR);
#pragma unroll
        for (int i = 0; i < 4; i++)
#pragma unroll
            for (int j = 0; j < 3; j++)
                wmma::mma_sync(acc[i][j], af[i], bfr[j], acc[i][j]);
    }
    __syncthreads();

#pragma unroll
    for (int i = 0; i < 4; i++)
#pragma unroll
        for (int j = 0; j < 3; j++)
            wmma::store_matrix_sync(&Cs[(wm * 64 + i * 16) * CST + wn * 48 + j * 16],
                                    acc[i][j], CST, wmma::mem_row_major);
    __syncthreads();

    for (int e = tid; e < 128 * (NTL / 8); e += 128) {
        int r  = e / (NTL / 8);
        int c8 = (e % (NTL / 8)) * 8;
        int m  = m0 + r;
        int nb = n0 + c8;
        const float* crow = &Cs[r * CST + c8];
        float4 a = *(const float4*)&crow[0];
        float4 bq = *(const float4*)&crow[4];
        float4 ba = *(const float4*)&bias[nb];
        float4 bb = *(const float4*)&bias[nb + 4];
        float vv[8] = {a.x + ba.x, a.y + ba.y, a.z + ba.z, a.w + ba.w,
                       bq.x + bb.x, bq.y + bb.y, bq.z + bb.z, bq.w + bb.w};

        if constexpr (EPI == 0) {
            int sel  = nb / Cv;
            int w2   = nb - sel * Cv;
            int head = w2 >> 5, d = w2 & 31;
            int win = m / NT, tok = m - win * NT;
            __nv_bfloat16* dst =
                (sel == 0 ? g_Q : sel == 1 ? g_K : g_V) +
                ((size_t)(win * HEADS + head) * NT + tok) * HD + d;
            const float sc = (sel == 0) ? SCALE : 1.f;
            __nv_bfloat16 o[8];
#pragma unroll
            for (int u = 0; u < 8; u++) o[u] = __float2bfloat16(vv[u] * sc);
            *(uint4*)dst = *(const uint4*)o;
        } else if constexpr (EPI == 1) {
            int win = m / NT, tok = m - win * NT;
            int bi = win >> 6, wi = win & 63;
            int wh = wi >> 3, ww = wi & 7;
            int ih = tok / WS, iw = tok - ih * WS;
            int r2 = (wh * WS + ih + SS) % Hv;
            int c2 = (ww * WS + iw + SS) % Wv;
            size_t pos = ((size_t)bi * Lv + r2 * Wv + c2) * Cv + nb;
#pragma unroll
            for (int u = 0; u < 8; u += 4) {
                float4 xv = *(const float4*)&xin[pos + u];
                float4 o = make_float4(vv[u] + xv.x, vv[u + 1] + xv.y,
                                       vv[u + 2] + xv.z, vv[u + 3] + xv.w);
                *(float4*)&g_x1[pos + u] = o;
            }
        } else {
            size_t pos = (size_t)m * MLPD + nb;
            __nv_bfloat16 o[8];
#pragma unroll
            for (int u = 0; u < 8; u++) {
                float t = vv[u];
                o[u] = __float2bfloat16(0.5f * t * (1.f + erff(t * 0.70710678118654752f)));
            }
            *(uint4*)&g_mid[pos] = *(const uint4*)o;
        }
    }
}

constexpr size_t wk_smem() {
    size_t lb = 128ull * (Cv + 8) * 2 + (size_t)Cv * (96 + 8) * 2;  // 91136
    size_t cb = 128ull * (96 + 4) * 4;                              // 51200
    return lb > cb ? lb : cb;
}

// ---- pipelined wmma GEMM K=768 (gemm3), 8 warps of 32x96 (NTL=192) ----
constexpr size_t gemm3_smem() {
    size_t stages = 3ull * (128 * 40 + 32 * (192 + 8)) * 2;  // 69120
    size_t cs     = 128ull * (192 + 4) * 4;                  // 100352
    return stages > cs ? stages : cs;
}

__global__ __launch_bounds__(256) void gemm3_k(const float* __restrict__ bias,
                                               float* __restrict__ outf) {
    constexpr int K   = MLPD;
    constexpr int N   = Cv;
    constexpr int BK  = 32;
    constexpr int NK  = K / BK;
    constexpr int NTL = 192;
    constexpr int NFR = 6;             // 96/16
    constexpr int BST = NTL + 8;       // 200
    constexpr int CST = NTL + 4;       // 196
    constexpr int ASZ = 128 * 40;
    constexpr int BSZ = 32 * BST;

    const __nv_bfloat16* __restrict__ A = g_mid;
    const __nv_bfloat16* __restrict__ Bm = g_w2;

    extern __shared__ __align__(16) unsigned char smbuf[];
    __nv_bfloat16* As = (__nv_bfloat16*)smbuf;
    __nv_bfloat16* Bs = (__nv_bfloat16*)(smbuf + 3 * ASZ * 2);
    float*         Cs = (float*)smbuf;

    const int tid = threadIdx.x;
    const int m0 = blockIdx.y * 128;
    const int warp = tid >> 5, wm = warp >> 1, wn = warp & 1;

    auto load_stage = [&](int kt, int stg) {
        int k0 = kt * BK;
        __nv_bfloat16* as = As + stg * ASZ;
        __nv_bfloat16* bs = Bs + stg * BSZ;
#pragma unroll
        for (int i = 0; i < 2; i++) {
            int id = tid + i * 256;
            int r = id >> 2, c8 = (id & 3) * 8;
            cp16(&as[r * 40 + c8], &A[(size_t)(m0 + r) * K + k0 + c8]);
        }
        for (int id = tid; id < 32 * (NTL / 8); id += 256) {
            int r = id / (NTL / 8), c8 = (id % (NTL / 8)) * 8;
            cp16(&bs[r * BST + c8], &Bm[(size_t)(k0 + r) * N + c8]);
        }
    };

    wmma::fragment<wmma::accumulator, 16, 16, 16, float> acc[2][NFR];
#pragma unroll
    for (int i = 0; i < 2; i++)
#pragma unroll
        for (int j = 0; j < NFR; j++) wmma::fill_fragment(acc[i][j], 0.f);

    load_stage(0, 0); CP_COMMIT();
    load_stage(1, 1); CP_COMMIT();

    for (int kt = 0; kt < NK; kt++) {
        CP_WAIT1();
        __syncthreads();
        const __nv_bfloat16* as = As + (kt % 3) * ASZ;
        const __nv_bfloat16* bs = Bs + (kt % 3) * BSZ;
#pragma unroll
        for (int kk = 0; kk < BK; kk += 16) {
            wmma::fragment<wmma::matrix_a, 16, 16, 16, __nv_bfloat16, wmma::row_major> af[2];
            wmma::fragment<wmma::matrix_b, 16, 16, 16, __nv_bfloat16, wmma::row_major> bfr[NFR];
            wmma::load_matrix_sync(af[0], &as[(wm * 32 + 0)  * 40 + kk], 40);
            wmma::load_matrix_sync(af[1], &as[(wm * 32 + 16) * 40 + kk], 40);
#pragma unroll
            for (int j = 0; j < NFR; j++)
                wmma::load_matrix_sync(bfr[j], &bs[kk * BST + wn * 96 + j * 16], BST);
#pragma unroll
            for (int i = 0; i < 2; i++)
#pragma unroll
                for (int j = 0; j < NFR; j++)
                    wmma::mma_sync(acc[i][j], af[i], bfr[j], acc[i][j]);
        }
        if (kt + 2 < NK) load_stage(kt + 2, (kt + 2) % 3);
        CP_COMMIT();
    }
    __syncthreads();

#pragma unroll
    for (int i = 0; i < 2; i++)
#pragma unroll
        for (int j = 0; j < NFR; j++)
            wmma::store_matrix_sync(&Cs[(wm * 32 + i * 16) * CST + wn * 96 + j * 16],
                                    acc[i][j], CST, wmma::mem_row_major);
    __syncthreads();

    for (int e = tid; e < 128 * (NTL / 8); e += 256) {
        int r  = e / (NTL / 8);
        int c8 = (e % (NTL / 8)) * 8;
        int m  = m0 + r;
        int nb = c8;
        const float* crow = &Cs[r * CST + c8];
        size_t pos = (size_t)m * Cv + nb;
#pragma unroll
        for (int u = 0; u < 8; u += 4) {
            float4 v  = *(const float4*)&crow[u];
            float4 bv = *(const float4*)&bias[nb + u];
            float4 xv = *(const float4*)&g_x1[pos + u];
            float4 o = make_float4(v.x + bv.x + xv.x, v.y + bv.y + xv.y,
                                   v.z + bv.z + xv.z, v.w + bv.w + xv.w);
            *(float4*)&outf[pos + u] = o;
        }
    }
}

// ---------------- launch ----------------
extern "C" void kernel_launch(void* const* d_in, const int* in_sizes, int n_in,
                              void* d_out, int out_size) {
    const float* x      = (const float*)d_in[0];
    const float* ln1_g  = (const float*)d_in[1];
    const float* ln1_b  = (const float*)d_in[2];
    const float* qkv_w  = (const float*)d_in[3];
    const float* qkv_b  = (const float*)d_in[4];
    const float* proj_w = (const float*)d_in[5];
    const float* proj_b = (const float*)d_in[6];
    const float* rpb    = (const float*)d_in[7];
    const float* ln2_g  = (const float*)d_in[8];
    const float* ln2_b  = (const float*)d_in[9];
    const float* mlp_w1 = (const float*)d_in[10];
    const float* mlp_b1 = (const float*)d_in[11];
    const float* mlp_w2 = (const float*)d_in[12];
    const float* mlp_b2 = (const float*)d_in[13];
    float* out = (float*)d_out;

    constexpr size_t WK  = wk_smem();      // 91136
    constexpr size_t S3  = gemm3_smem();   // 100352
    cudaFuncSetAttribute(gemm_wk<0>, cudaFuncAttributeMaxDynamicSharedMemorySize, (int)WK);
    cudaFuncSetAttribute(gemm_wk<1>, cudaFuncAttributeMaxDynamicSharedMemorySize, (int)WK);
    cudaFuncSetAttribute(gemm_wk<2>, cudaFuncAttributeMaxDynamicSharedMemorySize, (int)WK);
    cudaFuncSetAttribute(gemm3_k,    cudaFuncAttributeMaxDynamicSharedMemorySize, (int)S3);
    cudaFuncSetAttribute(attn_wmma,  cudaFuncAttributeMaxDynamicSharedMemorySize, ATTN_SMEM);

    cvt_weights<<<432, 1024>>>(qkv_w, proj_w, mlp_w1, mlp_w2);
    bm_kernel<<<(64 * HEADS * NT * 52 + 255) / 256, 256>>>(rpb);
    ln1_kernel<<<MT / 8, 256>>>(x, ln1_g, ln1_b);
    gemm_wk<0><<<dim3(576 / 96, MT / 128), 128, WK>>>(qkv_b, nullptr);
    attn_wmma<<<Bv * 64, 256, ATTN_SMEM>>>();
    gemm_wk<1><<<dim3(192 / 96, MT / 128), 128, WK>>>(proj_b, x);
    ln2_kernel<<<MT / 8, 256>>>(ln2_g, ln2_b);
    gemm_wk<2><<<dim3(768 / 96, MT / 128), 128, WK>>>(mlp_b1, nullptr);
    gemm3_k<<<dim3(1, MT / 128), 256, S3>>>(mlp_b2, out);
}